// round 1
// baseline (speedup 1.0000x reference)
#include <cuda_runtime.h>

// Problem constants
#define B_      128
#define D_      128
#define NROWS   600000
#define KP1     4097          // K+1
#define INV_T   (1.0f / 0.07f)

// Grid partition for the fused kernel
constexpr int GATHER_CHUNKS = 16;                 // blocks per batch row b
constexpr int GATHER_BLOCKS = B_ * GATHER_CHUNKS; // 2048
constexpr int COPY_BLOCKS   = 2048;
constexpr int FIN_SCALE_BLOCKS = 2048;

// Global accumulators for Z_l / Z_ab (zeroed each launch by init kernel)
__device__ double g_sum_l;
__device__ double g_sum_ab;

__global__ void init_sums_kernel() {
    g_sum_l  = 0.0;
    g_sum_ab = 0.0;
}

// Fused kernel:
//   blocks [0, GATHER_BLOCKS)              : gather rows, dot, exp, raw logits + partial sums
//   blocks [GATHER_BLOCKS, +COPY_BLOCKS)   : stream-copy both memory banks to output
__global__ __launch_bounds__(256) void cmc_main_kernel(
    const float* __restrict__ l,
    const float* __restrict__ ab,
    const int*   __restrict__ idx,
    const float* __restrict__ mem_l,
    const float* __restrict__ mem_ab,
    float* __restrict__ out)
{
    float* out_l   = out;                                  // [B, KP1]
    float* out_ab  = out + (size_t)B_ * KP1;               // [B, KP1]
    float* out_ml  = out + (size_t)2 * B_ * KP1;           // [N, D]
    float* out_mab = out_ml + (size_t)NROWS * D_;          // [N, D]

    if (blockIdx.x < GATHER_BLOCKS) {
        const int b     = blockIdx.x / GATHER_CHUNKS;
        const int chunk = blockIdx.x % GATHER_CHUNKS;
        const int warp  = threadIdx.x >> 5;
        const int lane  = threadIdx.x & 31;
        const int w     = chunk * 8 + warp;   // 0..127: warp id within batch row b

        // Each lane owns elements [lane*4, lane*4+4) of the l / ab vectors.
        const float4 lv = reinterpret_cast<const float4*>(l  + b * D_)[lane];
        const float4 av = reinterpret_cast<const float4*>(ab + b * D_)[lane];

        double s_l = 0.0, s_ab = 0.0;

        for (int k = w; k < KP1; k += 128) {
            const int row = idx[b * KP1 + k];
            const float4 a = reinterpret_cast<const float4*>(mem_l  + (size_t)row * D_)[lane];
            const float4 c = reinterpret_cast<const float4*>(mem_ab + (size_t)row * D_)[lane];

            // out_ab uses dot(memory_l row, ab); out_l uses dot(memory_ab row, l)
            float dab = a.x * av.x + a.y * av.y + a.z * av.z + a.w * av.w;
            float dl  = c.x * lv.x + c.y * lv.y + c.z * lv.z + c.w * lv.w;

            #pragma unroll
            for (int off = 16; off > 0; off >>= 1) {
                dab += __shfl_xor_sync(0xffffffffu, dab, off);
                dl  += __shfl_xor_sync(0xffffffffu, dl,  off);
            }

            if (lane == 0) {
                const float el  = expf(dl  * INV_T);
                const float eab = expf(dab * INV_T);
                out_l [b * KP1 + k] = el;
                out_ab[b * KP1 + k] = eab;
                s_l  += (double)el;
                s_ab += (double)eab;
            }
        }

        if (lane == 0) {
            atomicAdd(&g_sum_l,  s_l);
            atomicAdd(&g_sum_ab, s_ab);
        }
    } else {
        // Streaming copy of both memory banks (float4 = 16B per thread per iter)
        const size_t tid      = (size_t)(blockIdx.x - GATHER_BLOCKS) * blockDim.x + threadIdx.x;
        const size_t nthreads = (size_t)COPY_BLOCKS * 256;
        const size_t total4   = (size_t)NROWS * D_ / 4;   // per bank

        const float4* s1 = reinterpret_cast<const float4*>(mem_l);
        const float4* s2 = reinterpret_cast<const float4*>(mem_ab);
        float4* d1 = reinterpret_cast<float4*>(out_ml);
        float4* d2 = reinterpret_cast<float4*>(out_mab);

        for (size_t i = tid; i < total4; i += nthreads) d1[i] = s1[i];
        for (size_t i = tid; i < total4; i += nthreads) d2[i] = s2[i];
    }
}

// Finalize:
//   blocks [0, B)       : momentum scatter-update of the y rows (with L2 renorm)
//   blocks [B, B+2048)  : scale out_l / out_ab by 1/Z
__global__ __launch_bounds__(256) void cmc_finalize_kernel(
    const float* __restrict__ l,
    const float* __restrict__ ab,
    const int*   __restrict__ y,
    const float* __restrict__ mem_l,
    const float* __restrict__ mem_ab,
    float* __restrict__ out)
{
    float* out_l   = out;
    float* out_ab  = out + (size_t)B_ * KP1;
    float* out_ml  = out + (size_t)2 * B_ * KP1;
    float* out_mab = out_ml + (size_t)NROWS * D_;

    if (blockIdx.x < B_) {
        const int b  = blockIdx.x;
        const int yb = y[b];
        // Duplicate-index semantics: last writer wins (JAX scatter order).
        bool skip = false;
        for (int j = b + 1; j < B_; j++) if (y[j] == yb) skip = true;
        if (skip) return;

        // 256 threads: warps 0-3 handle memory_l (elems 0..127),
        //              warps 4-7 handle memory_ab (elems 0..127).
        const int tid  = threadIdx.x;
        const int bank = tid >> 7;          // 0: l-bank, 1: ab-bank
        const int e    = tid & 127;

        const float* mem = bank ? mem_ab : mem_l;
        const float* vec = bank ? ab      : l;
        float* outm      = bank ? out_mab : out_ml;

        const float v = mem[(size_t)yb * D_ + e] * 0.5f + vec[b * D_ + e] * 0.5f;
        float s = v * v;
        #pragma unroll
        for (int off = 16; off > 0; off >>= 1)
            s += __shfl_xor_sync(0xffffffffu, s, off);

        __shared__ float part[8];
        if ((tid & 31) == 0) part[tid >> 5] = s;
        __syncthreads();

        const float tot = part[bank * 4 + 0] + part[bank * 4 + 1]
                        + part[bank * 4 + 2] + part[bank * 4 + 3];
        outm[(size_t)yb * D_ + e] = v / sqrtf(tot);
    } else {
        // Scale logits by 1/Z. Z = (sum / (B*(K+1))) * N  =>  scale = B*(K+1)/(sum*N)
        const float sc_l  = (float)((double)B_ * (double)KP1 / (g_sum_l  * (double)NROWS));
        const float sc_ab = (float)((double)B_ * (double)KP1 / (g_sum_ab * (double)NROWS));

        const size_t tid = (size_t)(blockIdx.x - B_) * 256 + threadIdx.x;
        const size_t nth = (size_t)FIN_SCALE_BLOCKS * 256;
        const size_t total = (size_t)B_ * KP1;

        for (size_t i = tid; i < total; i += nth) out_l[i]  *= sc_l;
        for (size_t i = tid; i < total; i += nth) out_ab[i] *= sc_ab;
    }
}

extern "C" void kernel_launch(void* const* d_in, const int* in_sizes, int n_in,
                              void* d_out, int out_size)
{
    const float* l      = (const float*)d_in[0];
    const float* ab     = (const float*)d_in[1];
    const int*   y      = (const int*)  d_in[2];
    const int*   idx    = (const int*)  d_in[3];
    const float* mem_l  = (const float*)d_in[4];
    const float* mem_ab = (const float*)d_in[5];
    float* out = (float*)d_out;

    init_sums_kernel<<<1, 1>>>();
    cmc_main_kernel<<<GATHER_BLOCKS + COPY_BLOCKS, 256>>>(l, ab, idx, mem_l, mem_ab, out);
    cmc_finalize_kernel<<<B_ + FIN_SCALE_BLOCKS, 256>>>(l, ab, y, mem_l, mem_ab, out);
}

// round 2
// speedup vs baseline: 1.2921x; 1.2921x over previous
#include <cuda_runtime.h>

// Problem constants
#define B_      128
#define D_      128
#define NROWS   600000
#define KP1     4097          // K+1
#define INV_T   (1.0f / 0.07f)
#define NENT    (B_ * KP1)    // 524,416 (b,k) entries

// Inverted-index parameters
#define SLOTS    10
#define OVF_CAP  16384

// Scratch (static device allocations — allowed)
__device__ int      g_count[NROWS];
__device__ unsigned g_slots[(size_t)NROWS * SLOTS];
__device__ unsigned g_ovf[OVF_CAP];
__device__ int      g_ovf_n;
__device__ double   g_sum_l;
__device__ double   g_sum_ab;

// ---------------------------------------------------------------------------
// 0) Zero the per-launch scratch
__global__ __launch_bounds__(256) void zero_kernel() {
    const int tid = blockIdx.x * 256 + threadIdx.x;
    if (tid < NROWS) g_count[tid] = 0;
    if (tid == 0) { g_sum_l = 0.0; g_sum_ab = 0.0; g_ovf_n = 0; }
}

// ---------------------------------------------------------------------------
// 1) Build inverted index: row -> packed (b<<13 | k) entries
__global__ __launch_bounds__(256) void build_kernel(const int* __restrict__ idx) {
    const int tid = blockIdx.x * 256 + threadIdx.x;
    if (tid >= NENT) return;
    const int b = tid / KP1;
    const int k = tid - b * KP1;
    const int r = idx[tid];
    const unsigned ent = ((unsigned)b << 13) | (unsigned)k;
    const int c = atomicAdd(&g_count[r], 1);
    if (c < SLOTS) {
        g_slots[(size_t)r * SLOTS + c] = ent;
    } else {
        const int o = atomicAdd(&g_ovf_n, 1);
        if (o < OVF_CAP) g_ovf[o] = ent;
    }
}

// ---------------------------------------------------------------------------
// 2) Fused streaming copy + inverted-gather dot/exp.
//    One warp per bank row per iteration. Bank rows are read ONCE (streaming),
//    dots computed in-register against l/ab (128 KB, L1-resident).
__global__ __launch_bounds__(256) void copy_dot_kernel(
    const float* __restrict__ l,
    const float* __restrict__ ab,
    const float* __restrict__ mem_l,
    const float* __restrict__ mem_ab,
    float* __restrict__ out)
{
    float* out_l   = out;                              // [B, KP1] raw exp
    float* out_ab  = out + (size_t)B_ * KP1;
    float* out_ml  = out + (size_t)2 * B_ * KP1;       // [N, D]
    float* out_mab = out_ml + (size_t)NROWS * D_;

    const int lane = threadIdx.x & 31;
    const int warp_g = (blockIdx.x * blockDim.x + threadIdx.x) >> 5;
    const int nwarps = (gridDim.x * blockDim.x) >> 5;

    double s_l = 0.0, s_ab = 0.0;

    for (int r = warp_g; r < NROWS; r += nwarps) {
        const float4* srcA = reinterpret_cast<const float4*>(mem_l  + (size_t)r * D_);
        const float4* srcC = reinterpret_cast<const float4*>(mem_ab + (size_t)r * D_);
        const float4 a = __ldcs(srcA + lane);   // streaming: evict-first
        const float4 c = __ldcs(srcC + lane);
        __stcs(reinterpret_cast<float4*>(out_ml  + (size_t)r * D_) + lane, a);
        __stcs(reinterpret_cast<float4*>(out_mab + (size_t)r * D_) + lane, c);

        int n = g_count[r];
        if (n > SLOTS) n = SLOTS;
        for (int e = 0; e < n; e++) {
            const unsigned ent = g_slots[(size_t)r * SLOTS + e];
            const int b = ent >> 13;
            const int k = ent & 8191;
            const float4 av = reinterpret_cast<const float4*>(ab + b * D_)[lane];
            const float4 lv = reinterpret_cast<const float4*>(l  + b * D_)[lane];

            float dab = a.x * av.x + a.y * av.y + a.z * av.z + a.w * av.w;
            float dl  = c.x * lv.x + c.y * lv.y + c.z * lv.z + c.w * lv.w;
            #pragma unroll
            for (int off = 16; off > 0; off >>= 1) {
                dab += __shfl_xor_sync(0xffffffffu, dab, off);
                dl  += __shfl_xor_sync(0xffffffffu, dl,  off);
            }
            if (lane == 0) {
                const float el  = expf(dl  * INV_T);
                const float eab = expf(dab * INV_T);
                out_l [b * KP1 + k] = el;
                out_ab[b * KP1 + k] = eab;
                s_l  += (double)el;
                s_ab += (double)eab;
            }
        }
    }

    if (lane == 0 && (s_l != 0.0 || s_ab != 0.0)) {
        atomicAdd(&g_sum_l,  s_l);
        atomicAdd(&g_sum_ab, s_ab);
    }
}

// ---------------------------------------------------------------------------
// 3) Overflow safety net (expected empty): gather-style dot for spilled entries
__global__ __launch_bounds__(256) void overflow_kernel(
    const float* __restrict__ l,
    const float* __restrict__ ab,
    const int*   __restrict__ idx,
    const float* __restrict__ mem_l,
    const float* __restrict__ mem_ab,
    float* __restrict__ out)
{
    const int novf = g_ovf_n < OVF_CAP ? g_ovf_n : OVF_CAP;
    if (novf == 0) return;

    float* out_l  = out;
    float* out_ab = out + (size_t)B_ * KP1;

    const int lane = threadIdx.x & 31;
    const int warp_g = (blockIdx.x * blockDim.x + threadIdx.x) >> 5;
    const int nwarps = (gridDim.x * blockDim.x) >> 5;

    double s_l = 0.0, s_ab = 0.0;
    for (int i = warp_g; i < novf; i += nwarps) {
        const unsigned ent = g_ovf[i];
        const int b = ent >> 13;
        const int k = ent & 8191;
        const int r = idx[b * KP1 + k];
        const float4 a  = reinterpret_cast<const float4*>(mem_l  + (size_t)r * D_)[lane];
        const float4 c  = reinterpret_cast<const float4*>(mem_ab + (size_t)r * D_)[lane];
        const float4 av = reinterpret_cast<const float4*>(ab + b * D_)[lane];
        const float4 lv = reinterpret_cast<const float4*>(l  + b * D_)[lane];
        float dab = a.x * av.x + a.y * av.y + a.z * av.z + a.w * av.w;
        float dl  = c.x * lv.x + c.y * lv.y + c.z * lv.z + c.w * lv.w;
        #pragma unroll
        for (int off = 16; off > 0; off >>= 1) {
            dab += __shfl_xor_sync(0xffffffffu, dab, off);
            dl  += __shfl_xor_sync(0xffffffffu, dl,  off);
        }
        if (lane == 0) {
            const float el  = expf(dl  * INV_T);
            const float eab = expf(dab * INV_T);
            out_l [b * KP1 + k] = el;
            out_ab[b * KP1 + k] = eab;
            s_l  += (double)el;
            s_ab += (double)eab;
        }
    }
    if (lane == 0 && (s_l != 0.0 || s_ab != 0.0)) {
        atomicAdd(&g_sum_l,  s_l);
        atomicAdd(&g_sum_ab, s_ab);
    }
}

// ---------------------------------------------------------------------------
// 4) Finalize: momentum scatter-update (L2 renorm) + Z-scaling of logits
__global__ __launch_bounds__(256) void finalize_kernel(
    const float* __restrict__ l,
    const float* __restrict__ ab,
    const int*   __restrict__ y,
    const float* __restrict__ mem_l,
    const float* __restrict__ mem_ab,
    float* __restrict__ out)
{
    float* out_l   = out;
    float* out_ab  = out + (size_t)B_ * KP1;
    float* out_ml  = out + (size_t)2 * B_ * KP1;
    float* out_mab = out_ml + (size_t)NROWS * D_;

    if (blockIdx.x < B_) {
        const int b  = blockIdx.x;
        const int yb = y[b];
        // Duplicate-index semantics: last writer wins (JAX scatter order).
        bool skip = false;
        for (int j = b + 1; j < B_; j++) if (y[j] == yb) skip = true;
        if (skip) return;

        const int tid  = threadIdx.x;
        const int bank = tid >> 7;      // 0: l-bank, 1: ab-bank
        const int e    = tid & 127;

        const float* mem = bank ? mem_ab : mem_l;
        const float* vec = bank ? ab      : l;
        float* outm      = bank ? out_mab : out_ml;

        const float v = mem[(size_t)yb * D_ + e] * 0.5f + vec[b * D_ + e] * 0.5f;
        float s = v * v;
        #pragma unroll
        for (int off = 16; off > 0; off >>= 1)
            s += __shfl_xor_sync(0xffffffffu, s, off);

        __shared__ float part[8];
        if ((tid & 31) == 0) part[tid >> 5] = s;
        __syncthreads();

        const float tot = part[bank * 4 + 0] + part[bank * 4 + 1]
                        + part[bank * 4 + 2] + part[bank * 4 + 3];
        outm[(size_t)yb * D_ + e] = v / sqrtf(tot);
    } else {
        // scale = B*(K+1) / (sum * N)
        const float sc_l  = (float)((double)B_ * (double)KP1 / (g_sum_l  * (double)NROWS));
        const float sc_ab = (float)((double)B_ * (double)KP1 / (g_sum_ab * (double)NROWS));

        const size_t tid = (size_t)(blockIdx.x - B_) * 256 + threadIdx.x;
        const size_t nth = (size_t)2048 * 256;
        const size_t total = (size_t)B_ * KP1;

        for (size_t i = tid; i < total; i += nth) out_l[i]  *= sc_l;
        for (size_t i = tid; i < total; i += nth) out_ab[i] *= sc_ab;
    }
}

extern "C" void kernel_launch(void* const* d_in, const int* in_sizes, int n_in,
                              void* d_out, int out_size)
{
    const float* l      = (const float*)d_in[0];
    const float* ab     = (const float*)d_in[1];
    const int*   y      = (const int*)  d_in[2];
    const int*   idx    = (const int*)  d_in[3];
    const float* mem_l  = (const float*)d_in[4];
    const float* mem_ab = (const float*)d_in[5];
    float* out = (float*)d_out;

    zero_kernel<<<(NROWS + 255) / 256, 256>>>();
    build_kernel<<<(NENT + 255) / 256, 256>>>(idx);
    copy_dot_kernel<<<4096, 256>>>(l, ab, mem_l, mem_ab, out);
    overflow_kernel<<<16, 256>>>(l, ab, idx, mem_l, mem_ab, out);
    finalize_kernel<<<B_ + 2048, 256>>>(l, ab, y, mem_l, mem_ab, out);
}